// round 6
// baseline (speedup 1.0000x reference)
#include <cuda_runtime.h>
#include <math.h>

// ---------------------------------------------------------------------------
// Problem constants
// ---------------------------------------------------------------------------
#define BATCH 16
#define NH    128
#define L0    16384
#define KS    4
#define STRIDE 2
#define DEPTHS 13
#define LMAX  8192
#define CIN   129           // 128 h channels + 1 depth channel

#define T_OUT 16            // output positions per block
#define TPT   8             // t's per thread (two halves of 128 threads)
#define TIN   (2*T_OUT + 2) // 34 input positions per tile
#define NSLOT 4             // cp.async ring slots (prefetch distance 3)

typedef unsigned long long ull;

// ---------------------------------------------------------------------------
// Device scratch (static, allocation-free)
// ---------------------------------------------------------------------------
__device__ float  g_bufA[(size_t)BATCH * NH * LMAX];
__device__ float  g_bufB[(size_t)BATCH * NH * LMAX];
__device__ float4 g_W4[CIN * 3 * NH];        // [c][gate][o] -> (k0,k1,k2,k3)
__device__ float  g_capture[BATCH * NH];
__device__ int    g_Nseq[BATCH][DEPTHS + 1];
__device__ int    g_finish[BATCH];
__device__ int    g_rank[BATCH];

// ---------------------------------------------------------------------------
// f32x2 helpers
// ---------------------------------------------------------------------------
__device__ __forceinline__ ull fma2(ull a, ull b, ull c)
{
    ull d;
    asm("fma.rn.f32x2 %0, %1, %2, %3;" : "=l"(d) : "l"(a), "l"(b), "l"(c));
    return d;
}
__device__ __forceinline__ void unpack2f(ull v, float& lo, float& hi)
{
    asm("mov.b64 {%0, %1}, %2;" : "=f"(lo), "=f"(hi) : "l"(v));
}

// ---------------------------------------------------------------------------
// Prep: N recurrence, finish depth, stable rank
// ---------------------------------------------------------------------------
__global__ void prep_meta_kernel(const int* __restrict__ N)
{
    __shared__ int fin[BATCH];
    int b = threadIdx.x;
    if (b < BATCH) {
        int n = N[b];
        g_Nseq[b][0] = n;
        int f = DEPTHS - 1;
        bool done = false;
        #pragma unroll
        for (int d = 0; d < DEPTHS; ++d) {
            int m = n - KS; if (m < 0) m = 0;
            n = (m + 1) / 2 + 1;
            g_Nseq[b][d + 1] = n;
            if (!done && n <= 1) { f = d; done = true; }
        }
        fin[b] = f;
        g_finish[b] = f;
    }
    __syncthreads();
    if (b < BATCH) {
        int f = fin[b];
        int r = 0;
        #pragma unroll
        for (int j = 0; j < BATCH; ++j)
            if (fin[j] < f || (fin[j] == f && j < b)) r++;
        g_rank[b] = r;
    }
}

// ---------------------------------------------------------------------------
// Prep: repack W [384][129][4] -> g_W4[(c*3+gate)*128+o] = float4(k0..k3)
// ---------------------------------------------------------------------------
__global__ void prep_wt_kernel(const float* __restrict__ W)
{
    int i = blockIdx.x * blockDim.x + threadIdx.x;
    if (i < CIN * 3 * NH) {
        int o    = i & 127;
        int gate = (i >> 7) % 3;
        int c    = i / (3 * NH);
        int j    = gate * NH + o;
        const float4* src = reinterpret_cast<const float4*>(W);
        g_W4[i] = src[j * CIN + c];
    }
}

// ---------------------------------------------------------------------------
// One depth step (R2 skeleton + per-thread cp.async weight pipeline).
// 256 threads = 128 o x 2 halves of 8 t's. Each thread cp.async's the 3
// float4 weight vectors it will itself consume 3 iterations later.
// ---------------------------------------------------------------------------
__global__ __launch_bounds__(256, 3)
void conv_step_kernel(const float* __restrict__ hin,
                      int insel, int outsel,
                      int in_stride, int Lc, int Lout,
                      int depth, float logd,
                      const float* __restrict__ bias)
{
    const int b  = blockIdx.y;
    const int t0 = blockIdx.x * T_OUT;

    const int Nn = g_Nseq[b][depth + 1];
    if (t0 >= Nn) return;   // whole tile dead downstream

    const float* in = (insel == 0) ? hin : (insel == 1 ? g_bufA : g_bufB);
    float* out = (outsel == 1) ? g_bufA : g_bufB;

    // dynamic smem: tile[CIN][TIN] (17544B) | wbuf[8][NSLOT][3][32] float4 (49152B)
    extern __shared__ __align__(16) float sdyn[];
    float*  tile = sdyn;                                   // [CIN][TIN]
    float4* wbuf = reinterpret_cast<float4*>(sdyn + CIN * TIN + 2); // pad to 16B

    const int tid  = threadIdx.x;
    const int o    = tid & 127;
    const int lane = tid & 31;
    const int warp = tid >> 5;

    // per-thread wbuf base: [warp][slot][gate][lane]
    float4* wslot = wbuf + ((warp * NSLOT) * 3) * 32 + lane;
    // slot stride = 3*32 float4; gate stride = 32 float4
    #define WB(slot, gate) wslot[((slot) * 3 + (gate)) * 32]

    // gmem weight base for this o
    const float4* wg = g_W4 + o;

    // ---- prologue: prefetch weights for c = 0,1,2 ----
    #pragma unroll
    for (int s = 0; s < 3; ++s) {
        unsigned sm0 = (unsigned)__cvta_generic_to_shared(&WB(s, 0));
        unsigned sm1 = (unsigned)__cvta_generic_to_shared(&WB(s, 1));
        unsigned sm2 = (unsigned)__cvta_generic_to_shared(&WB(s, 2));
        const float4* g0 = wg + (s * 3 + 0) * NH;
        const float4* g1 = wg + (s * 3 + 1) * NH;
        const float4* g2 = wg + (s * 3 + 2) * NH;
        asm volatile("cp.async.cg.shared.global [%0], [%1], 16;" :: "r"(sm0), "l"(g0));
        asm volatile("cp.async.cg.shared.global [%0], [%1], 16;" :: "r"(sm1), "l"(g1));
        asm volatile("cp.async.cg.shared.global [%0], [%1], 16;" :: "r"(sm2), "l"(g2));
        asm volatile("cp.async.commit_group;");
    }

    // ---- load x tile ----
    const int V = min(Lc, g_Nseq[b][depth]);
    const float* inb = in + (size_t)b * NH * in_stride;
    for (int i = tid; i < CIN * TIN; i += 256) {
        int c = i / TIN;
        int x = i - c * TIN;
        int pos = 2 * t0 + x;
        float v = 0.0f;
        if (pos < V) v = (c < NH) ? inb[(size_t)c * in_stride + pos] : logd;
        tile[i] = v;
    }
    __syncthreads();

    const int half = tid >> 7;
    const int tl0  = half * TPT;

    ull accl[TPT], accr[TPT], accg[TPT];
    #pragma unroll
    for (int tt = 0; tt < TPT; ++tt) { accl[tt] = 0ull; accr[tt] = 0ull; accg[tt] = 0ull; }

    #pragma unroll 1
    for (int c = 0; c < CIN; ++c) {
        // stage for this c is complete once <= 2 groups remain in flight
        asm volatile("cp.async.wait_group 2;");
        const int slot = c & (NSLOT - 1);

        const ulonglong2 wl = *reinterpret_cast<const ulonglong2*>(&WB(slot, 0));
        const ulonglong2 wr = *reinterpret_cast<const ulonglong2*>(&WB(slot, 1));
        const ulonglong2 wgv = *reinterpret_cast<const ulonglong2*>(&WB(slot, 2));

        const ull* xr = reinterpret_cast<const ull*>(tile + c * TIN + 2 * tl0);
        ull x0 = xr[0];
        #pragma unroll
        for (int tt = 0; tt < TPT; ++tt) {
            ull x1 = xr[tt + 1];
            accl[tt] = fma2(wl.x,  x0, accl[tt]);
            accl[tt] = fma2(wl.y,  x1, accl[tt]);
            accr[tt] = fma2(wr.x,  x0, accr[tt]);
            accr[tt] = fma2(wr.y,  x1, accr[tt]);
            accg[tt] = fma2(wgv.x, x0, accg[tt]);
            accg[tt] = fma2(wgv.y, x1, accg[tt]);
            x0 = x1;
        }

        // prefetch c+3 into the slot just freed (self-consumed -> no barrier)
        const int cn = c + 3;
        if (cn < CIN) {
            const int sl = cn & (NSLOT - 1);
            unsigned sm0 = (unsigned)__cvta_generic_to_shared(&WB(sl, 0));
            unsigned sm1 = (unsigned)__cvta_generic_to_shared(&WB(sl, 1));
            unsigned sm2 = (unsigned)__cvta_generic_to_shared(&WB(sl, 2));
            const float4* g0 = wg + (cn * 3 + 0) * NH;
            const float4* g1 = wg + (cn * 3 + 1) * NH;
            const float4* g2 = wg + (cn * 3 + 2) * NH;
            asm volatile("cp.async.cg.shared.global [%0], [%1], 16;" :: "r"(sm0), "l"(g0));
            asm volatile("cp.async.cg.shared.global [%0], [%1], 16;" :: "r"(sm1), "l"(g1));
            asm volatile("cp.async.cg.shared.global [%0], [%1], 16;" :: "r"(sm2), "l"(g2));
        }
        asm volatile("cp.async.commit_group;");
    }

    const float bl = bias[o], br = bias[NH + o], bg = bias[2 * NH + o];
    const int fin_here = (g_finish[b] == depth);
    float* outb = out + ((size_t)b * NH + o) * LMAX;

    #pragma unroll
    for (int tt = 0; tt < TPT; ++tt) {
        int t = t0 + tl0 + tt;
        if (t < Lout) {
            float lo, hi;
            unpack2f(accl[tt], lo, hi); float l  = lo + hi + bl;
            unpack2f(accr[tt], lo, hi); float rr = lo + hi + br;
            unpack2f(accg[tt], lo, hi); float ga = lo + hi + bg;
            float gv = 1.0f / (1.0f + __expf(-ga));
            float rv = tanhf(rr);
            float hn = l * gv + rv * (1.0f - gv);
            outb[t] = hn;
            if (t == 0 && fin_here) g_capture[b * NH + o] = hn;
        }
    }
    #undef WB
}

// ---------------------------------------------------------------------------
// Final: out[rank[b]] = capture[b]
// ---------------------------------------------------------------------------
__global__ void finalize_kernel(float* __restrict__ out)
{
    int b = blockIdx.x;
    int o = threadIdx.x;
    out[g_rank[b] * NH + o] = g_capture[b * NH + o];
}

// ---------------------------------------------------------------------------
// Launch
// ---------------------------------------------------------------------------
extern "C" void kernel_launch(void* const* d_in, const int* in_sizes, int n_in,
                              void* d_out, int out_size)
{
    const float* h    = (const float*)d_in[0];
    const int*   N    = (const int*)  d_in[1];
    const float* W    = (const float*)d_in[2];
    const float* bias = (const float*)d_in[3];
    float* out = (float*)d_out;

    // dynamic smem: tile (17544B) + 16B pad + wbuf (49152B)
    const int SMEM_DYN = (CIN * TIN + 2) * (int)sizeof(float)
                       + 8 * NSLOT * 3 * 32 * (int)sizeof(float4);
    static int attr_set = 0;
    cudaFuncSetAttribute(conv_step_kernel,
                         cudaFuncAttributeMaxDynamicSharedMemorySize, SMEM_DYN);
    (void)attr_set;

    prep_meta_kernel<<<1, 32>>>(N);
    prep_wt_kernel<<<(CIN * 3 * NH + 255) / 256, 256>>>(W);

    static const int Lin[DEPTHS]   = {16384, 8191, 4095, 2047, 1023, 511, 255,
                                      127, 63, 31, 15, 7, 3};
    static const int LoutA[DEPTHS] = {8191, 4095, 2047, 1023, 511, 255, 127,
                                      63, 31, 15, 7, 3, 1};

    for (int d = 0; d < DEPTHS; ++d) {
        int insel  = (d == 0) ? 0 : ((d & 1) ? 1 : 2);
        int outsel = (d & 1) ? 2 : 1;
        int in_stride = (d == 0) ? L0 : LMAX;
        float logd = log1pf((float)d);
        dim3 grid((LoutA[d] + T_OUT - 1) / T_OUT, BATCH);
        conv_step_kernel<<<grid, 256, SMEM_DYN>>>(h, insel, outsel, in_stride,
                                                  Lin[d], LoutA[d], d, logd, bias);
    }

    finalize_kernel<<<BATCH, NH>>>(out);
}